// round 15
// baseline (speedup 1.0000x reference)
#include <cuda_runtime.h>
#include <cfloat>
#include <math.h>
#include <cstdint>

// Problem constants (fixed by the benchmark)
#define BB   2
#define CC   2
#define NN   1024
#define HH   8
#define FF   64
#define FIN2 (HH*FF)          // 512
#define NSL  (BB*CC*HH)       // 32 attention slices
#define NCH  (CC*HH)          // 16 weight slices
#define L2E  1.4426950408889634f

// ---------------- scratch (device globals: allocation-free) ----------------
__device__ unsigned int g_mask[BB*NN*(NN/32)];            // packed valid-edge bits (incl self loops)
__device__ float g_hp[(size_t)NSL*NN*FF];                 // h_prime for current layer
__device__ float g_s [NSL*NN];                            // src scores
__device__ float g_d [NSL*NN];                            // dst scores
__device__ float g_rml[NSL*NN];                           // rowmax * log2(e)
__device__ float g_x1[(size_t)BB*CC*NN*FIN2];             // layer-1 output (elu, head-flattened)
__device__ float g_o2[(size_t)NSL*NN*FF];                 // layer-2 attention output (pre head-mean)
// pre-split weights, packed bf16x2 hi/lo in B-fragment layout [ch][f][kpair]
__device__ uint32_t g_w1h[NCH*FF*32],  g_w1l[NCH*FF*32];   // FIN=64  -> 32 kpairs
__device__ uint32_t g_w2h[NCH*FF*256], g_w2l[NCH*FF*256];  // FIN=512 -> 256 kpairs

// ---------------- helpers ----------------
__device__ __forceinline__ float ex2f(float x){
    float r; asm("ex2.approx.f32 %0, %1;" : "=f"(r) : "f"(x)); return r;
}
__device__ __forceinline__ void cpasync16(unsigned smem, const void* g){
    asm volatile("cp.async.cg.shared.global [%0], [%1], 16;" :: "r"(smem), "l"(g));
}
__device__ __forceinline__ void cpasync_commit(){ asm volatile("cp.async.commit_group;"); }
__device__ __forceinline__ void cpasync_wait0(){ asm volatile("cp.async.wait_group 0;"); }

// pack two floats -> bf16x2 (hi_elem goes to upper half, lo_elem to lower half)
__device__ __forceinline__ uint32_t packbf2(float hi_elem, float lo_elem){
    uint32_t r;
    asm("cvt.rn.bf16x2.f32 %0, %1, %2;" : "=r"(r) : "f"(hi_elem), "f"(lo_elem));
    return r;
}
// split a (lo,hi) float pair into packed bf16x2 hi and lo-correction words
__device__ __forceinline__ void splitbf2(float v0, float v1, uint32_t &hi, uint32_t &lo){
    hi = packbf2(v1, v0);
    float h0 = __uint_as_float(hi << 16);
    float h1 = __uint_as_float(hi & 0xFFFF0000u);
    lo = packbf2(v1 - h1, v0 - h0);
}

// m16n8k16 bf16 HMMA (sm_80+ path; legal on plain sm_103 target)
__device__ __forceinline__ void mma_bf16(float* d, const uint32_t* a, uint32_t b0, uint32_t b1){
    asm volatile(
        "mma.sync.aligned.m16n8k16.row.col.f32.bf16.bf16.f32 "
        "{%0,%1,%2,%3}, {%4,%5,%6,%7}, {%8,%9}, {%0,%1,%2,%3};"
        : "+f"(d[0]), "+f"(d[1]), "+f"(d[2]), "+f"(d[3])
        : "r"(a[0]), "r"(a[1]), "r"(a[2]), "r"(a[3]), "r"(b0), "r"(b1));
}

// ---------------- kernel 0: pre-split weights into bf16 hi/lo B-layout ----------------
// w: [ch][k][f] fp32 -> wh/wl: [ch][f][kp] packed bf16x2 (k pair along k)
template<int FIN>
__global__ void split_w_kernel(const float* __restrict__ w,
                               uint32_t* __restrict__ wh, uint32_t* __restrict__ wl){
    const int KP = FIN/2;
    int idx = blockIdx.x*256 + threadIdx.x;        // over NCH*FF*KP
    int kp = idx % KP;
    int f  = (idx / KP) % FF;
    int ch = idx / (KP*FF);
    const float* wb = w + ((size_t)ch*FIN + 2*kp)*FF + f;
    uint32_t hi, lo;
    splitbf2(wb[0], wb[FF], hi, lo);
    wh[idx] = hi;
    wl[idx] = lo;
}

// ---------------- kernel 1: pack adjacency (+self loops) into bitmask ----------------
__global__ void pack_mask_kernel(const int* __restrict__ adj){
    int n = blockIdx.x, b = blockIdx.y, m = threadIdx.x;   // block of 1024 threads
    bool valid = (adj[((size_t)b*NN + n)*NN + m] != 0) || (m == n);
    unsigned bits = __ballot_sync(0xffffffffu, valid);
    if ((m & 31) == 0) g_mask[((size_t)b*NN + n)*32 + (m >> 5)] = bits;
}

// ---------------- kernel 2: h_prime = x @ w via mma.sync bf16 (+ tanh -> s,d) ----------------
// grid (NSL, 16), block 256 (8 warps). 64 rows x 64 feats, k chunks of 64.
// A = x (converted to bf16 hi/lo at staging, [n][kp] stride 36).
// B = w (pre-split in global, cp.async copied, [f][kp] stride 36).
// Warp tile 16x32 (rg=wrp&3 rows, fh=wrp>>2 feats); 3xbf16 per k16 step.
template<int FIN, bool FROMX1>
__global__ __launch_bounds__(256, 4) void gemm_mma_kernel(
    const float* __restrict__ xin,
    const uint32_t* __restrict__ wh, const uint32_t* __restrict__ wl,
    const float* __restrict__ a_src, const float* __restrict__ a_dst)
{
    __shared__ uint32_t ahi[64*36], alo[64*36];     // x operand pairs (9 KB each)
    __shared__ uint32_t bhi_s[64*36], blo_s[64*36]; // w operand pairs (9 KB each)
    __shared__ float as_s[64], ad_s[64];
    __shared__ float ssum[64][2], dsum[64][2];

    const int sl = blockIdx.x, n0 = blockIdx.y*64;
    const int b = sl/(CC*HH), c = (sl/HH)%CC, h = sl%HH;
    const int ch = c*HH + h;
    const int tid = threadIdx.x, lane = tid & 31, wrp = tid >> 5;
    const int gid = lane >> 2, t4 = lane & 3;
    const int rg = wrp & 3, fh = wrp >> 2;

    const float* x = FROMX1 ? (const float*)g_x1 : xin;
    const float* xbase = x + ((size_t)(b*CC + c)*NN + n0)*FIN;
    const uint32_t* whb = wh + (size_t)ch*FF*(FIN/2);
    const uint32_t* wlb = wl + (size_t)ch*FF*(FIN/2);

    if (tid < 64){
        as_s[tid] = a_src[ch*FF + tid];
        ad_s[tid] = a_dst[ch*FF + tid];
    }

    float dacc[4][4];
    #pragma unroll
    for (int nt = 0; nt < 4; nt++)
        #pragma unroll
        for (int i = 0; i < 4; i++) dacc[nt][i] = 0.f;

    const unsigned bhi_sm = (unsigned)__cvta_generic_to_shared(bhi_s);
    const unsigned blo_sm = (unsigned)__cvta_generic_to_shared(blo_s);
    const int q = tid & 7;                      // kp quad (kp0 = 4q), covers k 8q..8q+7

    for (int kc = 0; kc < FIN/64; kc++){
        if (kc > 0) __syncthreads();            // prior MMA done reading tiles

        // ---- B: cp.async pre-split weights (layout copy, zero ALU) ----
        #pragma unroll
        for (int it = 0; it < 2; it++){
            const int f = (tid >> 3) + 32*it;
            const size_t src = (size_t)f*(FIN/2) + kc*32 + 4*q;
            cpasync16(bhi_sm + (unsigned)(f*36 + 4*q)*4, whb + src);
            cpasync16(blo_sm + (unsigned)(f*36 + 4*q)*4, wlb + src);
        }
        cpasync_commit();

        // ---- A: load x tile, split to bf16 hi/lo pairs ----
        #pragma unroll
        for (int it = 0; it < 2; it++){
            const int n = (tid >> 3) + 32*it;
            const float4* src = (const float4*)(xbase + (size_t)n*FIN + kc*64 + 8*q);
            float4 xa = src[0], xb = src[1];
            uint32_t hi[4], lo[4];
            splitbf2(xa.x, xa.y, hi[0], lo[0]);
            splitbf2(xa.z, xa.w, hi[1], lo[1]);
            splitbf2(xb.x, xb.y, hi[2], lo[2]);
            splitbf2(xb.z, xb.w, hi[3], lo[3]);
            *(uint4*)&ahi[n*36 + 4*q] = make_uint4(hi[0], hi[1], hi[2], hi[3]);
            *(uint4*)&alo[n*36 + 4*q] = make_uint4(lo[0], lo[1], lo[2], lo[3]);
        }

        cpasync_wait0();
        __syncthreads();                        // operand tiles ready

        // ---- MMA: 16x32 warp tile, k=64 in 4 k16-steps, 3xbf16 ----
        const uint32_t* ea_hi = ahi + (16*rg + gid)*36;
        const uint32_t* ea_lo = alo + (16*rg + gid)*36;
        #pragma unroll
        for (int kk = 0; kk < 4; kk++){
            const int kp = 8*kk + t4;
            uint32_t ah[4], al[4];
            ah[0] = ea_hi[kp];          ah[1] = ea_hi[8*36 + kp];
            ah[2] = ea_hi[kp + 4];      ah[3] = ea_hi[8*36 + kp + 4];
            al[0] = ea_lo[kp];          al[1] = ea_lo[8*36 + kp];
            al[2] = ea_lo[kp + 4];      al[3] = ea_lo[8*36 + kp + 4];
            #pragma unroll
            for (int nt = 0; nt < 4; nt++){
                const int cb = (32*fh + 8*nt + gid)*36;
                uint32_t b0 = bhi_s[cb + kp], b1 = bhi_s[cb + kp + 4];
                uint32_t c0 = blo_s[cb + kp], c1 = blo_s[cb + kp + 4];
                mma_bf16(dacc[nt], ah, b0, b1);
                mma_bf16(dacc[nt], ah, c0, c1);
                mma_bf16(dacc[nt], al, b0, b1);
            }
        }
    }

    // ---- epilogue: store h_prime + tanh-weighted score partials ----
    const int r0 = 16*rg + gid, r1 = r0 + 8;
    float sp0 = 0.f, dp0 = 0.f, sp1 = 0.f, dp1 = 0.f;
    #pragma unroll
    for (int nt = 0; nt < 4; nt++){
        const int col = 32*fh + 8*nt + 2*t4;
        float v00 = dacc[nt][0], v01 = dacc[nt][1];
        float v10 = dacc[nt][2], v11 = dacc[nt][3];
        *(float2*)&g_hp[((size_t)sl*NN + n0 + r0)*FF + col] = make_float2(v00, v01);
        *(float2*)&g_hp[((size_t)sl*NN + n0 + r1)*FF + col] = make_float2(v10, v11);
        float t00 = tanhf(v00), t01 = tanhf(v01);
        float t10 = tanhf(v10), t11 = tanhf(v11);
        float a0 = as_s[col], a1 = as_s[col+1];
        float e0 = ad_s[col], e1 = ad_s[col+1];
        sp0 = fmaf(t00, a0, fmaf(t01, a1, sp0));
        dp0 = fmaf(t00, e0, fmaf(t01, e1, dp0));
        sp1 = fmaf(t10, a0, fmaf(t11, a1, sp1));
        dp1 = fmaf(t10, e0, fmaf(t11, e1, dp1));
    }
    // reduce over the t4 quad (lanes gid*4 + t4)
    #pragma unroll
    for (int o = 1; o <= 2; o <<= 1){
        sp0 += __shfl_xor_sync(0xffffffffu, sp0, o);
        dp0 += __shfl_xor_sync(0xffffffffu, dp0, o);
        sp1 += __shfl_xor_sync(0xffffffffu, sp1, o);
        dp1 += __shfl_xor_sync(0xffffffffu, dp1, o);
    }
    if (t4 == 0){
        ssum[r0][fh] = sp0;  dsum[r0][fh] = dp0;
        ssum[r1][fh] = sp1;  dsum[r1][fh] = dp1;
    }
    __syncthreads();
    if (tid < 64){
        g_s[sl*NN + n0 + tid] = ssum[tid][0] + ssum[tid][1];
        g_d[sl*NN + n0 + tid] = dsum[tid][0] + dsum[tid][1];
    }
}

// ---------------- kernel 3: exact row max (leaky is monotone => leaky(s + dmax)) ----------------
__global__ __launch_bounds__(256) void rowmax_kernel(){
    __shared__ float d_sw[1024];
    const int sl = blockIdx.x, n0 = blockIdx.y*128;
    const int b = sl/(CC*HH);
    const int tid = threadIdx.x, lane = tid & 31, wrp = tid >> 5;

    for (int i = tid; i < 1024; i += 256){
        int w = i >> 5, j = i & 31;
        d_sw[(w << 5) + ((j + w) & 31)] = g_d[sl*NN + i];
    }
    __syncthreads();

    const unsigned* mb = g_mask + (size_t)b*NN*32;
    for (int r = 0; r < 16; r++){
        const int n = n0 + wrp*16 + r;
        unsigned word = mb[(size_t)n*32 + lane];
        float dm = -FLT_MAX;
        #pragma unroll
        for (int i = 0; i < 32; i++){
            float v = d_sw[(lane << 5) + ((i + lane) & 31)];
            if ((word >> i) & 1u) dm = fmaxf(dm, v);
        }
        #pragma unroll
        for (int o = 16; o; o >>= 1) dm = fmaxf(dm, __shfl_xor_sync(0xffffffffu, dm, o));
        if (lane == 0){
            float s = g_s[sl*NN + n];
            float r0 = s + dm; r0 = (r0 >= 0.f) ? r0 : 0.2f*r0;
            g_rml[sl*NN + n] = r0 * L2E;
        }
    }
}

// ---------------- kernel 4: masked softmax + P @ h_prime via mma.sync bf16 (3-term) ----------------
// (unchanged from R14 — validated at 84.6us/layer)
template<bool LAYER1>
__global__ __launch_bounds__(256, 4) void attn_mma_kernel(){
    __shared__ uint32_t ehi[64*36], elo[64*36];     // A operand pairs (9 KB each)
    __shared__ uint32_t bhi_s[64*36], blo_s[64*36]; // B operand pairs (9 KB each)
    __shared__ float d_s[1024];
    __shared__ float s_s[64];
    __shared__ float rml_s[64];
    __shared__ float linv_s[64];

    const int sl = blockIdx.x, n0 = blockIdx.y*64;
    const int b = sl/(CC*HH), c = (sl/HH)%CC, h = sl%HH;
    const int tid = threadIdx.x, lane = tid & 31, wrp = tid >> 5;
    const int row0 = wrp*8;
    const int gid = lane >> 2, t4 = lane & 3;
    const int rg = wrp & 3, fh = wrp >> 2;

    for (int i = tid; i < 1024; i += 256) d_s[i] = g_d[sl*NN + i];
    if (tid < 64){
        s_s[tid]   = g_s  [sl*NN + n0 + tid];
        rml_s[tid] = g_rml[sl*NN + n0 + tid];
    }

    float lsum[8];
    #pragma unroll
    for (int r = 0; r < 8; r++) lsum[r] = 0.f;

    float dacc[4][4];
    #pragma unroll
    for (int nt = 0; nt < 4; nt++)
        #pragma unroll
        for (int i = 0; i < 4; i++) dacc[nt][i] = 0.f;

    const unsigned* mbase = g_mask + ((size_t)b*NN + n0)*32;
    const float* hpsl = g_hp + (size_t)sl*NN*FF;

    const int cf0 = tid & 63, ckq0 = tid >> 6;
    const int cf1 = cf0, ckq1 = ckq0 + 4;

    __syncthreads();

    for (int t = 0; t < 16; t++){
        const int m0 = t*64;

        // ---- hp -> bf16 hi/lo B tiles ----
        float v0[8], v1[8];
        #pragma unroll
        for (int mm = 0; mm < 8; mm++)
            v0[mm] = hpsl[(size_t)(m0 + 8*ckq0 + mm)*FF + cf0];
        #pragma unroll
        for (int mm = 0; mm < 8; mm++)
            v1[mm] = hpsl[(size_t)(m0 + 8*ckq1 + mm)*FF + cf1];
        {
            uint32_t hi[4], lo[4];
            #pragma unroll
            for (int p = 0; p < 4; p++) splitbf2(v0[2*p], v0[2*p+1], hi[p], lo[p]);
            *(uint4*)&bhi_s[cf0*36 + 4*ckq0] = make_uint4(hi[0], hi[1], hi[2], hi[3]);
            *(uint4*)&blo_s[cf0*36 + 4*ckq0] = make_uint4(lo[0], lo[1], lo[2], lo[3]);
            #pragma unroll
            for (int p = 0; p < 4; p++) splitbf2(v1[2*p], v1[2*p+1], hi[p], lo[p]);
            *(uint4*)&bhi_s[cf1*36 + 4*ckq1] = make_uint4(hi[0], hi[1], hi[2], hi[3]);
            *(uint4*)&blo_s[cf1*36 + 4*ckq1] = make_uint4(lo[0], lo[1], lo[2], lo[3]);
        }

        unsigned mword = 0u;
        if (lane < 16)
            mword = mbase[(size_t)(row0 + (lane >> 1))*32 + t*2 + (lane & 1)];

        const float2 dd = *(const float2*)&d_s[m0 + 2*lane];
        const unsigned shft = (2*lane) & 31;
        #pragma unroll
        for (int r = 0; r < 8; r++){
            const int row = row0 + r;
            unsigned mwa = __shfl_sync(0xffffffffu, mword, 2*r);
            unsigned mwb = __shfl_sync(0xffffffffu, mword, 2*r + 1);
            unsigned sel = (lane < 16) ? mwa : mwb;
            unsigned bits = (sel >> shft) & 3u;
            float s = s_s[row], rml = rml_s[row];
            float x0 = s + dd.x; x0 = (x0 >= 0.f) ? x0 : 0.2f*x0;
            float x1 = s + dd.y; x1 = (x1 >= 0.f) ? x1 : 0.2f*x1;
            float e0 = (bits & 1u) ? ex2f(fmaf(x0, L2E, -rml)) : 0.f;
            float e1 = (bits & 2u) ? ex2f(fmaf(x1, L2E, -rml)) : 0.f;
            lsum[r] += e0 + e1;
            uint32_t hi, lo;
            splitbf2(e0, e1, hi, lo);
            ehi[row*36 + lane] = hi;
            elo[row*36 + lane] = lo;
        }
        __syncthreads();

        const uint32_t* ea_hi = ehi + (16*rg + gid)*36;
        const uint32_t* ea_lo = elo + (16*rg + gid)*36;
        #pragma unroll
        for (int kk = 0; kk < 4; kk++){
            const int kp = 8*kk + t4;
            uint32_t ah[4], al[4];
            ah[0] = ea_hi[kp];          ah[1] = ea_hi[8*36 + kp];
            ah[2] = ea_hi[kp + 4];      ah[3] = ea_hi[8*36 + kp + 4];
            al[0] = ea_lo[kp];          al[1] = ea_lo[8*36 + kp];
            al[2] = ea_lo[kp + 4];      al[3] = ea_lo[8*36 + kp + 4];
            #pragma unroll
            for (int nt = 0; nt < 4; nt++){
                const int cb = (32*fh + 8*nt + gid)*36;
                uint32_t b0 = bhi_s[cb + kp], b1 = bhi_s[cb + kp + 4];
                uint32_t c0 = blo_s[cb + kp], c1 = blo_s[cb + kp + 4];
                mma_bf16(dacc[nt], ah, b0, b1);
                mma_bf16(dacc[nt], ah, c0, c1);
                mma_bf16(dacc[nt], al, b0, b1);
            }
        }
        __syncthreads();
    }

    #pragma unroll
    for (int r = 0; r < 8; r++){
        float v = lsum[r];
        #pragma unroll
        for (int o = 16; o; o >>= 1) v += __shfl_xor_sync(0xffffffffu, v, o);
        if (lane == 0) linv_s[row0 + r] = 1.f / v;
    }
    __syncthreads();

    const int r0 = 16*rg + gid, r1 = r0 + 8;
    const float inv0 = linv_s[r0];
    const float inv1 = linv_s[r1];
    const int ng0 = n0 + r0, ng1 = n0 + r1;
    #pragma unroll
    for (int nt = 0; nt < 4; nt++){
        const int col = 32*fh + 8*nt + 2*t4;
        float v00 = dacc[nt][0]*inv0, v01 = dacc[nt][1]*inv0;
        float v10 = dacc[nt][2]*inv1, v11 = dacc[nt][3]*inv1;
        if (LAYER1){
            v00 = (v00 > 0.f) ? v00 : expm1f(v00);
            v01 = (v01 > 0.f) ? v01 : expm1f(v01);
            v10 = (v10 > 0.f) ? v10 : expm1f(v10);
            v11 = (v11 > 0.f) ? v11 : expm1f(v11);
            float* base = &g_x1[((size_t)(b*CC + c)*NN)*FIN2 + h*FF + col];
            *(float2*)(base + (size_t)ng0*FIN2) = make_float2(v00, v01);
            *(float2*)(base + (size_t)ng1*FIN2) = make_float2(v10, v11);
        } else {
            float* base = &g_o2[((size_t)sl*NN)*FF + col];
            *(float2*)(base + (size_t)ng0*FF) = make_float2(v00, v01);
            *(float2*)(base + (size_t)ng1*FF) = make_float2(v10, v11);
        }
    }
}

// ---------------- kernel 5: mean over heads ----------------
__global__ void reduce_mean_kernel(float* __restrict__ out){
    int idx = blockIdx.x*blockDim.x + threadIdx.x;          // B*C*N*F = 262144
    int f  = idx & 63;
    int nn = (idx >> 6) & (NN - 1);
    int bc = idx >> 16;
    float sum = 0.f;
    #pragma unroll
    for (int h = 0; h < HH; h++)
        sum += g_o2[(((size_t)bc*HH + h)*NN + nn)*FF + f];
    out[idx] = sum * (1.f / HH);
}

// ---------------- launch ----------------
extern "C" void kernel_launch(void* const* d_in, const int* in_sizes, int n_in,
                              void* d_out, int out_size)
{
    const float* x   = (const float*)d_in[0];
    const int*   adj = (const int*)  d_in[1];
    const float* w1  = (const float*)d_in[2];
    const float* as1 = (const float*)d_in[3];
    const float* ad1 = (const float*)d_in[4];
    const float* w2  = (const float*)d_in[5];
    const float* as2 = (const float*)d_in[6];
    const float* ad2 = (const float*)d_in[7];
    float* out = (float*)d_out;

    split_w_kernel<64>  <<<(NCH*FF*32 )/256, 256>>>(w1, g_w1h, g_w1l);
    split_w_kernel<FIN2><<<(NCH*FF*256)/256, 256>>>(w2, g_w2h, g_w2l);
    pack_mask_kernel<<<dim3(NN, BB), 1024>>>(adj);

    gemm_mma_kernel<64,  false><<<dim3(NSL, 16), 256>>>(x, g_w1h, g_w1l, as1, ad1);
    rowmax_kernel<<<dim3(NSL, 8), 256>>>();
    attn_mma_kernel<true ><<<dim3(NSL, 16), 256>>>();

    gemm_mma_kernel<FIN2, true><<<dim3(NSL, 16), 256>>>(nullptr, g_w2h, g_w2l, as2, ad2);
    rowmax_kernel<<<dim3(NSL, 8), 256>>>();
    attn_mma_kernel<false><<<dim3(NSL, 16), 256>>>();

    reduce_mean_kernel<<<(BB*CC*NN*FF)/256, 256>>>(out);
}

// round 16
// speedup vs baseline: 3.6732x; 3.6732x over previous
#include <cuda_runtime.h>
#include <cfloat>
#include <math.h>
#include <cstdint>

// Problem constants (fixed by the benchmark)
#define BB   2
#define CC   2
#define NN   1024
#define HH   8
#define FF   64
#define FIN2 (HH*FF)          // 512
#define NSL  (BB*CC*HH)       // 32 attention slices
#define NCH  (CC*HH)          // 16 weight slices
#define L2E  1.4426950408889634f

// ---------------- scratch (device globals: allocation-free) ----------------
__device__ unsigned int g_mask[BB*NN*(NN/32)];            // packed valid-edge bits (incl self loops)
__device__ float g_hp[(size_t)NSL*NN*FF];                 // h_prime for current layer
__device__ float g_s [NSL*NN];                            // src scores
__device__ float g_d [NSL*NN];                            // dst scores
__device__ float g_rml[NSL*NN];                           // rowmax * log2(e)
__device__ float g_x1[(size_t)BB*CC*NN*FIN2];             // layer-1 output (elu, head-flattened)
__device__ float g_o2[(size_t)NSL*NN*FF];                 // layer-2 attention output (pre head-mean)

// ---------------- helpers ----------------
__device__ __forceinline__ float ex2f(float x){
    float r; asm("ex2.approx.f32 %0, %1;" : "=f"(r) : "f"(x)); return r;
}

// pack two floats -> bf16x2 (hi_elem goes to upper half, lo_elem to lower half)
__device__ __forceinline__ uint32_t packbf2(float hi_elem, float lo_elem){
    uint32_t r;
    asm("cvt.rn.bf16x2.f32 %0, %1, %2;" : "=r"(r) : "f"(hi_elem), "f"(lo_elem));
    return r;
}
// split a (lo,hi) float pair into packed bf16x2 hi and lo-correction words
__device__ __forceinline__ void splitbf2(float v0, float v1, uint32_t &hi, uint32_t &lo){
    hi = packbf2(v1, v0);
    float h0 = __uint_as_float(hi << 16);
    float h1 = __uint_as_float(hi & 0xFFFF0000u);
    lo = packbf2(v1 - h1, v0 - h0);
}

// m16n8k16 bf16 HMMA (sm_80+ path; legal on plain sm_103 target)
__device__ __forceinline__ void mma_bf16(float* d, const uint32_t* a, uint32_t b0, uint32_t b1){
    asm volatile(
        "mma.sync.aligned.m16n8k16.row.col.f32.bf16.bf16.f32 "
        "{%0,%1,%2,%3}, {%4,%5,%6,%7}, {%8,%9}, {%0,%1,%2,%3};"
        : "+f"(d[0]), "+f"(d[1]), "+f"(d[2]), "+f"(d[3])
        : "r"(a[0]), "r"(a[1]), "r"(a[2]), "r"(a[3]), "r"(b0), "r"(b1));
}

// ---------------- kernel 1: pack adjacency (+self loops) into bitmask ----------------
__global__ void pack_mask_kernel(const int* __restrict__ adj){
    int n = blockIdx.x, b = blockIdx.y, m = threadIdx.x;   // block of 1024 threads
    bool valid = (adj[((size_t)b*NN + n)*NN + m] != 0) || (m == n);
    unsigned bits = __ballot_sync(0xffffffffu, valid);
    if ((m & 31) == 0) g_mask[((size_t)b*NN + n)*32 + (m >> 5)] = bits;
}

// ---------------- kernel 2: h_prime = x @ w via mma.sync bf16 (+ tanh -> s,d) ----------------
// grid (NSL, 16), block 256 (8 warps). 64 rows x 64 feats, k chunks of 64.
// Staging uses the R14-attn-proven idiom ONLY: coalesced LDG fp32 -> splitbf2 -> STS.128.
// A = x ([n][kp] stride 36), B = w ([f][kp] stride 36). No cp.async, no pre-split.
// Warp tile 16x32 (rg=wrp&3 rows, fh=wrp>>2 feats); 3xbf16 per k16 step.
template<int FIN, bool FROMX1>
__global__ __launch_bounds__(256, 4) void gemm_mma_kernel(
    const float* __restrict__ xin, const float* __restrict__ w,
    const float* __restrict__ a_src, const float* __restrict__ a_dst)
{
    __shared__ uint32_t ahi[64*36], alo[64*36];     // x operand pairs (9 KB each)
    __shared__ uint32_t bhi_s[64*36], blo_s[64*36]; // w operand pairs (9 KB each)
    __shared__ float as_s[64], ad_s[64];
    __shared__ float ssum[64][2], dsum[64][2];

    const int sl = blockIdx.x, n0 = blockIdx.y*64;
    const int b = sl/(CC*HH), c = (sl/HH)%CC, h = sl%HH;
    const int ch = c*HH + h;
    const int tid = threadIdx.x, lane = tid & 31, wrp = tid >> 5;
    const int gid = lane >> 2, t4 = lane & 3;
    const int rg = wrp & 3, fh = wrp >> 2;

    const float* x = FROMX1 ? (const float*)g_x1 : xin;
    const float* xbase = x + ((size_t)(b*CC + c)*NN + n0)*FIN;
    const float* wbase = w + (size_t)ch*FIN*FF;

    if (tid < 64){
        as_s[tid] = a_src[ch*FF + tid];
        ad_s[tid] = a_dst[ch*FF + tid];
    }

    float dacc[4][4];
    #pragma unroll
    for (int nt = 0; nt < 4; nt++)
        #pragma unroll
        for (int i = 0; i < 4; i++) dacc[nt][i] = 0.f;

    // staging cell coords (attn idiom): 512 cells = 64 cols x 8 kp-quads, 2 cells/thread
    const int cf = tid & 63, ckq0 = tid >> 6, ckq1 = ckq0 + 4;

    for (int kc = 0; kc < FIN/64; kc++){
        if (kc > 0) __syncthreads();            // prior MMA done reading tiles

        // ---- B: w chunk [64k x 64f] -> bf16 hi/lo [f][kp] (coalesced LDG over f) ----
        {
            float wv0[8], wv1[8];
            #pragma unroll
            for (int mm = 0; mm < 8; mm++)
                wv0[mm] = wbase[(size_t)(kc*64 + 8*ckq0 + mm)*FF + cf];
            #pragma unroll
            for (int mm = 0; mm < 8; mm++)
                wv1[mm] = wbase[(size_t)(kc*64 + 8*ckq1 + mm)*FF + cf];
            uint32_t hi[4], lo[4];
            #pragma unroll
            for (int p = 0; p < 4; p++) splitbf2(wv0[2*p], wv0[2*p+1], hi[p], lo[p]);
            *(uint4*)&bhi_s[cf*36 + 4*ckq0] = make_uint4(hi[0], hi[1], hi[2], hi[3]);
            *(uint4*)&blo_s[cf*36 + 4*ckq0] = make_uint4(lo[0], lo[1], lo[2], lo[3]);
            #pragma unroll
            for (int p = 0; p < 4; p++) splitbf2(wv1[2*p], wv1[2*p+1], hi[p], lo[p]);
            *(uint4*)&bhi_s[cf*36 + 4*ckq1] = make_uint4(hi[0], hi[1], hi[2], hi[3]);
            *(uint4*)&blo_s[cf*36 + 4*ckq1] = make_uint4(lo[0], lo[1], lo[2], lo[3]);
        }

        // ---- A: x chunk [64n x 64k] -> bf16 hi/lo [n][kp] (row-contiguous LDG.128) ----
        {
            const float4* s0 = (const float4*)(xbase + (size_t)cf*FIN + kc*64 + 8*ckq0);
            const float4* s1 = (const float4*)(xbase + (size_t)cf*FIN + kc*64 + 8*ckq1);
            float4 xa = s0[0], xb = s0[1];
            float4 xc = s1[0], xd = s1[1];
            uint32_t hi[4], lo[4];
            splitbf2(xa.x, xa.y, hi[0], lo[0]);
            splitbf2(xa.z, xa.w, hi[1], lo[1]);
            splitbf2(xb.x, xb.y, hi[2], lo[2]);
            splitbf2(xb.z, xb.w, hi[3], lo[3]);
            *(uint4*)&ahi[cf*36 + 4*ckq0] = make_uint4(hi[0], hi[1], hi[2], hi[3]);
            *(uint4*)&alo[cf*36 + 4*ckq0] = make_uint4(lo[0], lo[1], lo[2], lo[3]);
            splitbf2(xc.x, xc.y, hi[0], lo[0]);
            splitbf2(xc.z, xc.w, hi[1], lo[1]);
            splitbf2(xd.x, xd.y, hi[2], lo[2]);
            splitbf2(xd.z, xd.w, hi[3], lo[3]);
            *(uint4*)&ahi[cf*36 + 4*ckq1] = make_uint4(hi[0], hi[1], hi[2], hi[3]);
            *(uint4*)&alo[cf*36 + 4*ckq1] = make_uint4(lo[0], lo[1], lo[2], lo[3]);
        }

        __syncthreads();                        // operand tiles ready

        // ---- MMA: 16x32 warp tile, k=64 in 4 k16-steps, 3xbf16 ----
        const uint32_t* ea_hi = ahi + (16*rg + gid)*36;
        const uint32_t* ea_lo = alo + (16*rg + gid)*36;
        #pragma unroll
        for (int kk = 0; kk < 4; kk++){
            const int kp = 8*kk + t4;
            uint32_t ah[4], al[4];
            ah[0] = ea_hi[kp];          ah[1] = ea_hi[8*36 + kp];
            ah[2] = ea_hi[kp + 4];      ah[3] = ea_hi[8*36 + kp + 4];
            al[0] = ea_lo[kp];          al[1] = ea_lo[8*36 + kp];
            al[2] = ea_lo[kp + 4];      al[3] = ea_lo[8*36 + kp + 4];
            #pragma unroll
            for (int nt = 0; nt < 4; nt++){
                const int cb = (32*fh + 8*nt + gid)*36;
                uint32_t b0 = bhi_s[cb + kp], b1 = bhi_s[cb + kp + 4];
                uint32_t c0 = blo_s[cb + kp], c1 = blo_s[cb + kp + 4];
                mma_bf16(dacc[nt], ah, b0, b1);
                mma_bf16(dacc[nt], ah, c0, c1);
                mma_bf16(dacc[nt], al, b0, b1);
            }
        }
    }

    // ---- epilogue: store h_prime + tanh-weighted score partials ----
    const int r0 = 16*rg + gid, r1 = r0 + 8;
    float sp0 = 0.f, dp0 = 0.f, sp1 = 0.f, dp1 = 0.f;
    #pragma unroll
    for (int nt = 0; nt < 4; nt++){
        const int col = 32*fh + 8*nt + 2*t4;
        float v00 = dacc[nt][0], v01 = dacc[nt][1];
        float v10 = dacc[nt][2], v11 = dacc[nt][3];
        *(float2*)&g_hp[((size_t)sl*NN + n0 + r0)*FF + col] = make_float2(v00, v01);
        *(float2*)&g_hp[((size_t)sl*NN + n0 + r1)*FF + col] = make_float2(v10, v11);
        float t00 = tanhf(v00), t01 = tanhf(v01);
        float t10 = tanhf(v10), t11 = tanhf(v11);
        float a0 = as_s[col], a1 = as_s[col+1];
        float e0 = ad_s[col], e1 = ad_s[col+1];
        sp0 = fmaf(t00, a0, fmaf(t01, a1, sp0));
        dp0 = fmaf(t00, e0, fmaf(t01, e1, dp0));
        sp1 = fmaf(t10, a0, fmaf(t11, a1, sp1));
        dp1 = fmaf(t10, e0, fmaf(t11, e1, dp1));
    }
    // reduce over the t4 quad (lanes gid*4 + t4)
    #pragma unroll
    for (int o = 1; o <= 2; o <<= 1){
        sp0 += __shfl_xor_sync(0xffffffffu, sp0, o);
        dp0 += __shfl_xor_sync(0xffffffffu, dp0, o);
        sp1 += __shfl_xor_sync(0xffffffffu, sp1, o);
        dp1 += __shfl_xor_sync(0xffffffffu, dp1, o);
    }
    if (t4 == 0){
        ssum[r0][fh] = sp0;  dsum[r0][fh] = dp0;
        ssum[r1][fh] = sp1;  dsum[r1][fh] = dp1;
    }
    __syncthreads();
    if (tid < 64){
        g_s[sl*NN + n0 + tid] = ssum[tid][0] + ssum[tid][1];
        g_d[sl*NN + n0 + tid] = dsum[tid][0] + dsum[tid][1];
    }
}

// ---------------- kernel 3: exact row max (leaky is monotone => leaky(s + dmax)) ----------------
__global__ __launch_bounds__(256) void rowmax_kernel(){
    __shared__ float d_sw[1024];
    const int sl = blockIdx.x, n0 = blockIdx.y*128;
    const int b = sl/(CC*HH);
    const int tid = threadIdx.x, lane = tid & 31, wrp = tid >> 5;

    for (int i = tid; i < 1024; i += 256){
        int w = i >> 5, j = i & 31;
        d_sw[(w << 5) + ((j + w) & 31)] = g_d[sl*NN + i];
    }
    __syncthreads();

    const unsigned* mb = g_mask + (size_t)b*NN*32;
    for (int r = 0; r < 16; r++){
        const int n = n0 + wrp*16 + r;
        unsigned word = mb[(size_t)n*32 + lane];
        float dm = -FLT_MAX;
        #pragma unroll
        for (int i = 0; i < 32; i++){
            float v = d_sw[(lane << 5) + ((i + lane) & 31)];
            if ((word >> i) & 1u) dm = fmaxf(dm, v);
        }
        #pragma unroll
        for (int o = 16; o; o >>= 1) dm = fmaxf(dm, __shfl_xor_sync(0xffffffffu, dm, o));
        if (lane == 0){
            float s = g_s[sl*NN + n];
            float r0 = s + dm; r0 = (r0 >= 0.f) ? r0 : 0.2f*r0;
            g_rml[sl*NN + n] = r0 * L2E;
        }
    }
}

// ---------------- kernel 4: masked softmax + P @ h_prime via mma.sync bf16 (3-term) ----------------
// (unchanged from R14 — validated at 84.6us/layer)
template<bool LAYER1>
__global__ __launch_bounds__(256, 4) void attn_mma_kernel(){
    __shared__ uint32_t ehi[64*36], elo[64*36];     // A operand pairs (9 KB each)
    __shared__ uint32_t bhi_s[64*36], blo_s[64*36]; // B operand pairs (9 KB each)
    __shared__ float d_s[1024];
    __shared__ float s_s[64];
    __shared__ float rml_s[64];
    __shared__ float linv_s[64];

    const int sl = blockIdx.x, n0 = blockIdx.y*64;
    const int b = sl/(CC*HH), c = (sl/HH)%CC, h = sl%HH;
    const int tid = threadIdx.x, lane = tid & 31, wrp = tid >> 5;
    const int row0 = wrp*8;
    const int gid = lane >> 2, t4 = lane & 3;
    const int rg = wrp & 3, fh = wrp >> 2;

    for (int i = tid; i < 1024; i += 256) d_s[i] = g_d[sl*NN + i];
    if (tid < 64){
        s_s[tid]   = g_s  [sl*NN + n0 + tid];
        rml_s[tid] = g_rml[sl*NN + n0 + tid];
    }

    float lsum[8];
    #pragma unroll
    for (int r = 0; r < 8; r++) lsum[r] = 0.f;

    float dacc[4][4];
    #pragma unroll
    for (int nt = 0; nt < 4; nt++)
        #pragma unroll
        for (int i = 0; i < 4; i++) dacc[nt][i] = 0.f;

    const unsigned* mbase = g_mask + ((size_t)b*NN + n0)*32;
    const float* hpsl = g_hp + (size_t)sl*NN*FF;

    const int cf0 = tid & 63, ckq0 = tid >> 6;
    const int cf1 = cf0, ckq1 = ckq0 + 4;

    __syncthreads();

    for (int t = 0; t < 16; t++){
        const int m0 = t*64;

        // ---- hp -> bf16 hi/lo B tiles ----
        float v0[8], v1[8];
        #pragma unroll
        for (int mm = 0; mm < 8; mm++)
            v0[mm] = hpsl[(size_t)(m0 + 8*ckq0 + mm)*FF + cf0];
        #pragma unroll
        for (int mm = 0; mm < 8; mm++)
            v1[mm] = hpsl[(size_t)(m0 + 8*ckq1 + mm)*FF + cf1];
        {
            uint32_t hi[4], lo[4];
            #pragma unroll
            for (int p = 0; p < 4; p++) splitbf2(v0[2*p], v0[2*p+1], hi[p], lo[p]);
            *(uint4*)&bhi_s[cf0*36 + 4*ckq0] = make_uint4(hi[0], hi[1], hi[2], hi[3]);
            *(uint4*)&blo_s[cf0*36 + 4*ckq0] = make_uint4(lo[0], lo[1], lo[2], lo[3]);
            #pragma unroll
            for (int p = 0; p < 4; p++) splitbf2(v1[2*p], v1[2*p+1], hi[p], lo[p]);
            *(uint4*)&bhi_s[cf1*36 + 4*ckq1] = make_uint4(hi[0], hi[1], hi[2], hi[3]);
            *(uint4*)&blo_s[cf1*36 + 4*ckq1] = make_uint4(lo[0], lo[1], lo[2], lo[3]);
        }

        unsigned mword = 0u;
        if (lane < 16)
            mword = mbase[(size_t)(row0 + (lane >> 1))*32 + t*2 + (lane & 1)];

        const float2 dd = *(const float2*)&d_s[m0 + 2*lane];
        const unsigned shft = (2*lane) & 31;
        #pragma unroll
        for (int r = 0; r < 8; r++){
            const int row = row0 + r;
            unsigned mwa = __shfl_sync(0xffffffffu, mword, 2*r);
            unsigned mwb = __shfl_sync(0xffffffffu, mword, 2*r + 1);
            unsigned sel = (lane < 16) ? mwa : mwb;
            unsigned bits = (sel >> shft) & 3u;
            float s = s_s[row], rml = rml_s[row];
            float x0 = s + dd.x; x0 = (x0 >= 0.f) ? x0 : 0.2f*x0;
            float x1 = s + dd.y; x1 = (x1 >= 0.f) ? x1 : 0.2f*x1;
            float e0 = (bits & 1u) ? ex2f(fmaf(x0, L2E, -rml)) : 0.f;
            float e1 = (bits & 2u) ? ex2f(fmaf(x1, L2E, -rml)) : 0.f;
            lsum[r] += e0 + e1;
            uint32_t hi, lo;
            splitbf2(e0, e1, hi, lo);
            ehi[row*36 + lane] = hi;
            elo[row*36 + lane] = lo;
        }
        __syncthreads();

        const uint32_t* ea_hi = ehi + (16*rg + gid)*36;
        const uint32_t* ea_lo = elo + (16*rg + gid)*36;
        #pragma unroll
        for (int kk = 0; kk < 4; kk++){
            const int kp = 8*kk + t4;
            uint32_t ah[4], al[4];
            ah[0] = ea_hi[kp];          ah[1] = ea_hi[8*36 + kp];
            ah[2] = ea_hi[kp + 4];      ah[3] = ea_hi[8*36 + kp + 4];
            al[0] = ea_lo[kp];          al[1] = ea_lo[8*36 + kp];
            al[2] = ea_lo[kp + 4];      al[3] = ea_lo[8*36 + kp + 4];
            #pragma unroll
            for (int nt = 0; nt < 4; nt++){
                const int cb = (32*fh + 8*nt + gid)*36;
                uint32_t b0 = bhi_s[cb + kp], b1 = bhi_s[cb + kp + 4];
                uint32_t c0 = blo_s[cb + kp], c1 = blo_s[cb + kp + 4];
                mma_bf16(dacc[nt], ah, b0, b1);
                mma_bf16(dacc[nt], ah, c0, c1);
                mma_bf16(dacc[nt], al, b0, b1);
            }
        }
        __syncthreads();
    }

    #pragma unroll
    for (int r = 0; r < 8; r++){
        float v = lsum[r];
        #pragma unroll
        for (int o = 16; o; o >>= 1) v += __shfl_xor_sync(0xffffffffu, v, o);
        if (lane == 0) linv_s[row0 + r] = 1.f / v;
    }
    __syncthreads();

    const int r0 = 16*rg + gid, r1 = r0 + 8;
    const float inv0 = linv_s[r0];
    const float inv1 = linv_s[r1];
    const int ng0 = n0 + r0, ng1 = n0 + r1;
    #pragma unroll
    for (int nt = 0; nt < 4; nt++){
        const int col = 32*fh + 8*nt + 2*t4;
        float v00 = dacc[nt][0]*inv0, v01 = dacc[nt][1]*inv0;
        float v10 = dacc[nt][2]*inv1, v11 = dacc[nt][3]*inv1;
        if (LAYER1){
            v00 = (v00 > 0.f) ? v00 : expm1f(v00);
            v01 = (v01 > 0.f) ? v01 : expm1f(v01);
            v10 = (v10 > 0.f) ? v10 : expm1f(v10);
            v11 = (v11 > 0.f) ? v11 : expm1f(v11);
            float* base = &g_x1[((size_t)(b*CC + c)*NN)*FIN2 + h*FF + col];
            *(float2*)(base + (size_t)ng0*FIN2) = make_float2(v00, v01);
            *(float2*)(base + (size_t)ng1*FIN2) = make_float2(v10, v11);
        } else {
            float* base = &g_o2[((size_t)sl*NN)*FF + col];
            *(float2*)(base + (size_t)ng0*FF) = make_float2(v00, v01);
            *(float2*)(base + (size_t)ng1*FF) = make_float2(v10, v11);
        }
    }
}

// ---------------- kernel 5: mean over heads ----------------
__global__ void reduce_mean_kernel(float* __restrict__ out){
    int idx = blockIdx.x*blockDim.x + threadIdx.x;          // B*C*N*F = 262144
    int f  = idx & 63;
    int nn = (idx >> 6) & (NN - 1);
    int bc = idx >> 16;
    float sum = 0.f;
    #pragma unroll
    for (int h = 0; h < HH; h++)
        sum += g_o2[(((size_t)bc*HH + h)*NN + nn)*FF + f];
    out[idx] = sum * (1.f / HH);
}

// ---------------- launch ----------------
extern "C" void kernel_launch(void* const* d_in, const int* in_sizes, int n_in,
                              void* d_out, int out_size)
{
    const float* x   = (const float*)d_in[0];
    const int*   adj = (const int*)  d_in[1];
    const float* w1  = (const float*)d_in[2];
    const float* as1 = (const float*)d_in[3];
    const float* ad1 = (const float*)d_in[4];
    const float* w2  = (const float*)d_in[5];
    const float* as2 = (const float*)d_in[6];
    const float* ad2 = (const float*)d_in[7];
    float* out = (float*)d_out;

    pack_mask_kernel<<<dim3(NN, BB), 1024>>>(adj);

    gemm_mma_kernel<64,  false><<<dim3(NSL, 16), 256>>>(x, w1, as1, ad1);
    rowmax_kernel<<<dim3(NSL, 8), 256>>>();
    attn_mma_kernel<true ><<<dim3(NSL, 16), 256>>>();

    gemm_mma_kernel<FIN2, true><<<dim3(NSL, 16), 256>>>(nullptr, w2, as2, ad2);
    rowmax_kernel<<<dim3(NSL, 8), 256>>>();
    attn_mma_kernel<false><<<dim3(NSL, 16), 256>>>();

    reduce_mean_kernel<<<(BB*CC*NN*FF)/256, 256>>>(out);
}